// round 7
// baseline (speedup 1.0000x reference)
#include <cuda_runtime.h>
#include <math.h>

// Problem constants
#define B_  2
#define C_  64
#define H_  128
#define W_  128
#define HW_ (H_*W_)          // 16384
#define HID 16
#define OFC 18
#define NPT 9
#define KTOT (C_*NPT)        // 576
#define PIXT (B_*HW_)        // 32768
#define HP_  130
#define WP_  130
#define HWP_ (HP_*WP_)       // 16900

// ---- device scratch (no runtime allocation allowed) ----
__device__ float g_f  [B_*HID*HW_];       // offset-branch feature [B,16,H,W]
__device__ float g_off[B_*OFC*HW_];       // offsets               [B,18,H,W]
__device__ float g_wt [KTOT*C_ + 64];     // permuted w_out: row R=(c*72+n*8+cil), col oc
__device__ float g_xp [B_*HWP_*C_ + 8];   // TRANSPOSED padded input [B][130*130][64]

// packed fp32x2 FMA (full-rate on sm_103a; scalar FFMA is half-rate)
#define FMA2(d,a,b) asm("fma.rn.f32x2 %0, %1, %2, %0;" : "+l"(d) : "l"(a), "l"(b))

// ============================================================
// K_padT: zero-pad + TRANSPOSE x into g_xp[b][hw_p][c]
//         (+ tail blocks: permute-transpose w_out into g_wt)
// ============================================================
#define PAD_BLKS (B_*HP_)
#define W0_BLKS  ((KTOT*C_ + 255)/256)
__global__ __launch_bounds__(256)
void k_padT(const float* __restrict__ x, const float* __restrict__ w) {
    int blk = blockIdx.x;
    int tid = threadIdx.x;
    if (blk < PAD_BLKS) {
        __shared__ float ts[WP_ * 65];     // [w][c] with pitch 65 (conflict-free)
        int b = blk / HP_, h = blk % HP_;
        if (h >= 1 && h <= H_) {
            const float* xr = x + (size_t)b * C_ * HW_ + (h - 1) * W_;
            for (int e = tid; e < C_ * W_; e += 256) {
                int c = e >> 7, w2 = e & 127;            // coalesced read along w
                ts[(w2 + 1) * 65 + c] = xr[c * HW_ + w2];
            }
            if (tid < 2 * C_) {                          // border columns
                int c = tid & 63, side = tid >> 6;
                ts[(side ? (WP_ - 1) * 65 : 0) + c] = 0.f;
            }
        } else {
            for (int e = tid; e < WP_ * C_; e += 256) {
                int w2 = e >> 6, c = e & 63;
                ts[w2 * 65 + c] = 0.f;
            }
        }
        __syncthreads();
        float* dst = g_xp + ((size_t)b * HP_ + h) * WP_ * C_;
        for (int e = tid; e < WP_ * C_; e += 256) {
            int w2 = e >> 6, c = e & 63;
            dst[e] = ts[w2 * 65 + c];                    // coalesced write along c
        }
    } else {
        int t = (blk - PAD_BLKS) * 256 + tid;
        if (t < KTOT * C_) {
            int oc = t / KTOT, k = t - oc * KTOT;        // k = ci*9 + n
            int ci = k / 9, n = k - ci * 9;
            int R = (ci >> 3) * 72 + n * 8 + (ci & 7);
            g_wt[R * C_ + oc] = w[t];
        }
    }
}

// ============================================================
// K1: f = relu(bn(conv1x1_{64->16}(x)))
// ============================================================
__global__ void k1_conv1(const float* __restrict__ x,
                         const float* __restrict__ w1,
                         const float* __restrict__ g1,
                         const float* __restrict__ b1,
                         const float* __restrict__ m1,
                         const float* __restrict__ v1) {
    __shared__ float ws[C_][HID];
    __shared__ float inv_s[HID], beta_s[HID];
    int tid = threadIdx.x;
    for (int e = tid; e < HID * C_; e += 256) {
        int o = e / C_, c = e % C_;
        ws[c][o] = w1[e];
    }
    if (tid < HID) {
        float inv = g1[tid] * rsqrtf(v1[tid] + 1e-5f);
        inv_s[tid] = inv;
        beta_s[tid] = b1[tid] - m1[tid] * inv;
    }
    __syncthreads();

    int p = blockIdx.x * 256 + tid;
    int b = p >> 14, hw = p & (HW_ - 1);
    const float* xb = x + (size_t)b * C_ * HW_ + hw;

    float acc[HID];
#pragma unroll
    for (int o = 0; o < HID; o++) acc[o] = 0.f;
    for (int c = 0; c < C_; c++) {
        float xv = xb[c * HW_];
#pragma unroll
        for (int o = 0; o < HID; o++) acc[o] += ws[c][o] * xv;
    }
    float* fb = g_f + (size_t)b * HID * HW_ + hw;
#pragma unroll
    for (int o = 0; o < HID; o++)
        fb[o * HW_] = fmaxf(acc[o] * inv_s[o] + beta_s[o], 0.f);
}

// ============================================================
// K2 (tiled): off = relu(bn3(1x1( relu(bn2(3x3(f))) )))
// ============================================================
__global__ __launch_bounds__(256)
void k2_offsets(const float* __restrict__ wdw,
                const float* __restrict__ g2, const float* __restrict__ b2,
                const float* __restrict__ m2, const float* __restrict__ v2,
                const float* __restrict__ wc2,
                const float* __restrict__ g3, const float* __restrict__ b3,
                const float* __restrict__ m3, const float* __restrict__ v3) {
    __shared__ float fs[HID * 18 * 18];
    __shared__ float wdw_s[OFC * HID * 9];
    __shared__ float wc2_s[OFC * OFC];
    __shared__ float inv2_s[OFC], beta2_s[OFC], inv3_s[OFC], beta3_s[OFC];
    int tid = threadIdx.x;

    int blk = blockIdx.x;
    int b = blk >> 6, t = blk & 63;
    int h0 = (t >> 3) << 4, w0 = (t & 7) << 4;

    for (int e = tid; e < OFC * HID * 9; e += 256) wdw_s[e] = wdw[e];
    for (int e = tid; e < OFC * OFC; e += 256)     wc2_s[e] = wc2[e];
    if (tid < OFC) {
        float i2 = g2[tid] * rsqrtf(v2[tid] + 1e-5f);
        inv2_s[tid] = i2; beta2_s[tid] = b2[tid] - m2[tid] * i2;
        float i3 = g3[tid] * rsqrtf(v3[tid] + 1e-5f);
        inv3_s[tid] = i3; beta3_s[tid] = b3[tid] - m3[tid] * i3;
    }

    const float* fb = g_f + (size_t)b * HID * HW_;
    for (int e = tid; e < HID * 324; e += 256) {
        int ci = e / 324, r = e - ci * 324;
        int hh = r / 18, ww = r - hh * 18;
        int h = h0 - 1 + hh, w = w0 - 1 + ww;
        float v = 0.f;
        if (h >= 0 && h < H_ && w >= 0 && w < W_)
            v = fb[ci * HW_ + h * W_ + w];
        fs[e] = v;
    }
    __syncthreads();

    int ty2 = tid >> 4, tx2 = tid & 15;
    float acc[OFC];
#pragma unroll
    for (int o = 0; o < OFC; o++) acc[o] = 0.f;

    for (int ci = 0; ci < HID; ci++) {
        float fv[9];
        const float* fsc = fs + ci * 324;
#pragma unroll
        for (int dh = 0; dh < 3; dh++)
#pragma unroll
            for (int dw = 0; dw < 3; dw++)
                fv[dh * 3 + dw] = fsc[(ty2 + dh) * 18 + (tx2 + dw)];
        const float* wp = wdw_s + ci * 9;
#pragma unroll
        for (int o = 0; o < OFC; o++) {
            const float* wo = wp + o * (HID * 9);
            float a = acc[o];
#pragma unroll
            for (int k = 0; k < 9; k++) a += wo[k] * fv[k];
            acc[o] = a;
        }
    }
    float tv[OFC];
#pragma unroll
    for (int o = 0; o < OFC; o++)
        tv[o] = fmaxf(acc[o] * inv2_s[o] + beta2_s[o], 0.f);

    int h = h0 + ty2, w = w0 + tx2;
    float* op = g_off + (size_t)b * OFC * HW_ + h * W_ + w;
#pragma unroll
    for (int o2 = 0; o2 < OFC; o2++) {
        float a = 0.f;
#pragma unroll
        for (int o = 0; o < OFC; o++) a += wc2_s[o2 * OFC + o] * tv[o];
        op[o2 * HW_] = fmaxf(a * inv3_s[o2] + beta3_s[o2], 0.f);
    }
}

// ============================================================
// K3: fused bilinear sampler (vectorized via [hw][c] layout) + SGEMM + residual
// ============================================================
#define A2N (72*128)
#define K3_SMEM (576*32 + 2*A2N*4)   // 18432 + 73728 = 92160

__global__ __launch_bounds__(256, 2)
void k3_main(const float* __restrict__ x, float* __restrict__ out) {
    extern __shared__ char smem[];
    int4*   idx_s = (int4*)smem;                   // [9][64], premultiplied by 64
    float4* wgt_s = (float4*)(smem + 9216);        // [9][64]
    float*  a2    = (float*)(smem + 18432);        // [2][72][128]

    int tid = threadIdx.x;
    int blk = blockIdx.x;
    int b = blk >> 8;
    int tile = blk & 255;
    int h0 = (tile >> 4) << 3;
    int w0 = (tile & 15) << 3;

    // ---- bilinear metadata: 64 px x 9 pts ----
    const float* offp = g_off + (size_t)b * OFC * HW_;
    for (int e = tid; e < 64 * NPT; e += 256) {
        int m = e / NPT, n = e - m * NPT;
        int h = h0 + (m >> 3), w = w0 + (m & 7);
        int hw = h * W_ + w;
        float offx = offp[n * HW_ + hw];
        float offy = offp[(NPT + n) * HW_ + hw];
        float px = (float)(h + 1) + (float)(n / 3 - 1) + offx;
        float py = (float)(w + 1) + (float)(n % 3 - 1) + offy;
        float flx = floorf(px), fly = floorf(py);
        float qltx = fminf(fmaxf(flx, 0.f), 129.f);
        float qlty = fminf(fmaxf(fly, 0.f), 129.f);
        float qrbx = fminf(fmaxf(flx + 1.f, 0.f), 129.f);
        float qrby = fminf(fmaxf(fly + 1.f, 0.f), 129.f);
        px = fminf(fmaxf(px, 0.f), 129.f);
        py = fminf(fmaxf(py, 0.f), 129.f);
        float gxl = 1.f + qltx - px, gxr = 1.f - qrbx + px;
        float gyl = 1.f + qlty - py, gyr = 1.f - qrby + py;
        float4 g;
        g.x = gxl * gyl; g.y = gxr * gyr; g.z = gxl * gyr; g.w = gxr * gyl;
        int ltx = (int)qltx, lty = (int)qlty, rbx = (int)qrbx, rby = (int)qrby;
        int4 id;
        id.x = (ltx * WP_ + lty) << 6;    // premultiplied by C_=64
        id.y = (rbx * WP_ + rby) << 6;
        id.z = (ltx * WP_ + rby) << 6;
        id.w = (rbx * WP_ + lty) << 6;
        idx_s[n * 64 + m] = id;
        wgt_s[n * 64 + m] = g;
    }
    __syncthreads();

    const float* xpb = g_xp + (size_t)b * HWP_ * C_;

    // ---- gather one chunk (8 channels) into buffer ----
    //   per sample: 4 corners x 2 float4 = 8 vector loads, 32 FMA, 8 dup stores
#define GATHER_CHUNK(ab, cc)                                                  \
    {                                                                         \
        const float* xpc = xpb + (cc) * 8;                                    \
        for (int e = tid; e < 576; e += 256) {                                \
            int n = e >> 6, m = e & 63;                                       \
            int4 id = idx_s[e];                                               \
            float4 g = wgt_s[e];                                              \
            const float4* plt = (const float4*)(xpc + id.x);                  \
            const float4* prb = (const float4*)(xpc + id.y);                  \
            const float4* plb = (const float4*)(xpc + id.z);                  \
            const float4* prt = (const float4*)(xpc + id.w);                  \
            float4 lt0 = plt[0], lt1 = plt[1];                                \
            float4 rb0 = prb[0], rb1 = prb[1];                                \
            float4 lb0 = plb[0], lb1 = plb[1];                                \
            float4 rt0 = prt[0], rt1 = prt[1];                                \
            float* dst = (ab) + ((n << 3) << 7) + (m << 1);                   \
            float v;                                                          \
            v = g.x*lt0.x + g.y*rb0.x + g.z*lb0.x + g.w*rt0.x;                \
            *(float2*)(dst + (0 << 7)) = make_float2(v, v);                   \
            v = g.x*lt0.y + g.y*rb0.y + g.z*lb0.y + g.w*rt0.y;                \
            *(float2*)(dst + (1 << 7)) = make_float2(v, v);                   \
            v = g.x*lt0.z + g.y*rb0.z + g.z*lb0.z + g.w*rt0.z;                \
            *(float2*)(dst + (2 << 7)) = make_float2(v, v);                   \
            v = g.x*lt0.w + g.y*rb0.w + g.z*lb0.w + g.w*rt0.w;                \
            *(float2*)(dst + (3 << 7)) = make_float2(v, v);                   \
            v = g.x*lt1.x + g.y*rb1.x + g.z*lb1.x + g.w*rt1.x;                \
            *(float2*)(dst + (4 << 7)) = make_float2(v, v);                   \
            v = g.x*lt1.y + g.y*rb1.y + g.z*lb1.y + g.w*rt1.y;                \
            *(float2*)(dst + (5 << 7)) = make_float2(v, v);                   \
            v = g.x*lt1.z + g.y*rb1.z + g.z*lb1.z + g.w*rt1.z;                \
            *(float2*)(dst + (6 << 7)) = make_float2(v, v);                   \
            v = g.x*lt1.w + g.y*rb1.w + g.z*lb1.w + g.w*rt1.w;                \
            *(float2*)(dst + (7 << 7)) = make_float2(v, v);                   \
        }                                                                     \
    }

    GATHER_CHUNK(a2, 0)

    int tx = tid & 15, ty = tid >> 4;
    unsigned long long acc[4][2];
#pragma unroll
    for (int i = 0; i < 4; i++) { acc[i][0] = 0ull; acc[i][1] = 0ull; }

    const int tyo = ty << 3;
    const int txo = tx << 2;

    // ---- pipelined chunk loop: gather(c+1) overlaps GEMM(c) ----
    for (int c = 0; c < 8; c++) {
        __syncthreads();

        if (c < 7) {
            float* ab = a2 + ((c + 1) & 1) * A2N;
            GATHER_CHUNK(ab, c + 1)
        }

        const float* ab = a2 + (c & 1) * A2N;
        const float* wp = g_wt + c * 72 * C_ + txo;   // permuted B rows (L2-hot)
#pragma unroll 8
        for (int k = 0; k < 72; k++) {
            ulonglong2 bb = *reinterpret_cast<const ulonglong2*>(wp + (k << 6));
            ulonglong2 aA = *reinterpret_cast<const ulonglong2*>(ab + (k << 7) + tyo);
            ulonglong2 aB = *reinterpret_cast<const ulonglong2*>(ab + (k << 7) + tyo + 4);
            FMA2(acc[0][0], aA.x, bb.x); FMA2(acc[0][1], aA.x, bb.y);
            FMA2(acc[1][0], aA.y, bb.x); FMA2(acc[1][1], aA.y, bb.y);
            FMA2(acc[2][0], aB.x, bb.x); FMA2(acc[2][1], aB.x, bb.y);
            FMA2(acc[3][0], aB.y, bb.x); FMA2(acc[3][1], aB.y, bb.y);
        }
    }

    // ---- epilogue: stage through smem (buf0 dead) for coalesced stores ----
    float* sa = a2;  // [oc][m]
#pragma unroll
    for (int pi = 0; pi < 4; pi++) {
        int m = (ty << 2) + pi;
#pragma unroll
        for (int j = 0; j < 2; j++) {
            unsigned long long v = acc[pi][j];
            float lo = __uint_as_float((unsigned)(v & 0xffffffffull));
            float hi = __uint_as_float((unsigned)(v >> 32));
            sa[(txo + 2 * j) * 64 + m]     = lo;
            sa[(txo + 2 * j + 1) * 64 + m] = hi;
        }
    }
    __syncthreads();

    for (int e = tid; e < 64 * 64; e += 256) {
        int oc = e >> 6, m = e & 63;
        int h = h0 + (m >> 3), w = w0 + (m & 7);
        int gi = ((b * C_ + oc) * H_ + h) * W_ + w;
        out[gi] = x[gi] + sa[e];
    }
}

// ============================================================
extern "C" void kernel_launch(void* const* d_in, const int* in_sizes, int n_in,
                              void* d_out, int out_size) {
    const float* x       = (const float*)d_in[0];
    const float* w_conv1 = (const float*)d_in[1];
    const float* g1 = (const float*)d_in[2];
    const float* b1 = (const float*)d_in[3];
    const float* m1 = (const float*)d_in[4];
    const float* v1 = (const float*)d_in[5];
    const float* w_dw = (const float*)d_in[6];
    const float* g2 = (const float*)d_in[7];
    const float* b2 = (const float*)d_in[8];
    const float* m2 = (const float*)d_in[9];
    const float* v2 = (const float*)d_in[10];
    const float* w_conv2 = (const float*)d_in[11];
    const float* g3 = (const float*)d_in[12];
    const float* b3 = (const float*)d_in[13];
    const float* m3 = (const float*)d_in[14];
    const float* v3 = (const float*)d_in[15];
    const float* w_out = (const float*)d_in[16];
    float* out = (float*)d_out;

    cudaFuncSetAttribute(k3_main, cudaFuncAttributeMaxDynamicSharedMemorySize, K3_SMEM);

    k_padT<<<PAD_BLKS + W0_BLKS, 256>>>(x, w_out);
    k1_conv1<<<PIXT / 256, 256>>>(x, w_conv1, g1, b1, m1, v1);
    k2_offsets<<<128, 256>>>(w_dw, g2, b2, m2, v2, w_conv2, g3, b3, m3, v3);
    k3_main<<<B_ * (H_ / 8) * (W_ / 8), 256, K3_SMEM>>>(x, out);
}

// round 8
// speedup vs baseline: 1.1649x; 1.1649x over previous
#include <cuda_runtime.h>
#include <math.h>

// Problem constants
#define B_  2
#define C_  64
#define H_  128
#define W_  128
#define HW_ (H_*W_)          // 16384
#define HID 16
#define OFC 18
#define NPT 9
#define KTOT (C_*NPT)        // 576
#define PIXT (B_*HW_)        // 32768
#define HP_  130
#define WP_  130
#define HWP_ (HP_*WP_)       // 16900

// ---- device scratch (no runtime allocation allowed) ----
__device__ float g_f  [B_*HID*HW_];       // offset-branch feature [B,16,H,W]
__device__ float g_off[B_*OFC*HW_];       // offsets               [B,18,H,W]
__device__ float g_wt [KTOT*C_ + 64];     // permuted w_out: row R=(c*72+n*8+cil), col oc
__device__ float g_xp [B_*HWP_*C_ + 8];   // TRANSPOSED padded input [B][130*130][64]

// packed fp32x2 FMA (full-rate on sm_103a; scalar FFMA is half-rate)
#define FMA2(d,a,b) asm("fma.rn.f32x2 %0, %1, %2, %0;" : "+l"(d) : "l"(a), "l"(b))

// ============================================================
// K_padT: zero-pad + TRANSPOSE x into g_xp[b][hw_p][c]
//         (+ tail blocks: permute-transpose w_out into g_wt)
// ============================================================
#define PAD_BLKS (B_*HP_)
#define W0_BLKS  ((KTOT*C_ + 255)/256)
__global__ __launch_bounds__(256)
void k_padT(const float* __restrict__ x, const float* __restrict__ w) {
    int blk = blockIdx.x;
    int tid = threadIdx.x;
    if (blk < PAD_BLKS) {
        __shared__ float ts[WP_ * 65];     // [w][c] pitch 65 (conflict-free)
        int b = blk / HP_, h = blk % HP_;
        if (h >= 1 && h <= H_) {
            const float* xr = x + (size_t)b * C_ * HW_ + (h - 1) * W_;
            for (int e = tid; e < C_ * W_; e += 256) {
                int c = e >> 7, w2 = e & 127;            // coalesced read along w
                ts[(w2 + 1) * 65 + c] = xr[c * HW_ + w2];
            }
            if (tid < 2 * C_) {                          // border columns
                int c = tid & 63, side = tid >> 6;
                ts[(side ? (WP_ - 1) * 65 : 0) + c] = 0.f;
            }
        } else {
            for (int e = tid; e < WP_ * C_; e += 256) {
                int w2 = e >> 6, c = e & 63;
                ts[w2 * 65 + c] = 0.f;
            }
        }
        __syncthreads();
        float* dst = g_xp + ((size_t)b * HP_ + h) * WP_ * C_;
        for (int e = tid; e < WP_ * C_; e += 256) {
            int w2 = e >> 6, c = e & 63;
            dst[e] = ts[w2 * 65 + c];                    // coalesced write along c
        }
    } else {
        int t = (blk - PAD_BLKS) * 256 + tid;
        if (t < KTOT * C_) {
            int oc = t / KTOT, k = t - oc * KTOT;        // k = ci*9 + n
            int ci = k / 9, n = k - ci * 9;
            int R = (ci >> 3) * 72 + n * 8 + (ci & 7);
            g_wt[R * C_ + oc] = w[t];
        }
    }
}

// ============================================================
// K1: f = relu(bn(conv1x1_{64->16}(x)))
// ============================================================
__global__ void k1_conv1(const float* __restrict__ x,
                         const float* __restrict__ w1,
                         const float* __restrict__ g1,
                         const float* __restrict__ b1,
                         const float* __restrict__ m1,
                         const float* __restrict__ v1) {
    __shared__ float ws[C_][HID];
    __shared__ float inv_s[HID], beta_s[HID];
    int tid = threadIdx.x;
    for (int e = tid; e < HID * C_; e += 256) {
        int o = e / C_, c = e % C_;
        ws[c][o] = w1[e];
    }
    if (tid < HID) {
        float inv = g1[tid] * rsqrtf(v1[tid] + 1e-5f);
        inv_s[tid] = inv;
        beta_s[tid] = b1[tid] - m1[tid] * inv;
    }
    __syncthreads();

    int p = blockIdx.x * 256 + tid;
    int b = p >> 14, hw = p & (HW_ - 1);
    const float* xb = x + (size_t)b * C_ * HW_ + hw;

    float acc[HID];
#pragma unroll
    for (int o = 0; o < HID; o++) acc[o] = 0.f;
    for (int c = 0; c < C_; c++) {
        float xv = xb[c * HW_];
#pragma unroll
        for (int o = 0; o < HID; o++) acc[o] += ws[c][o] * xv;
    }
    float* fb = g_f + (size_t)b * HID * HW_ + hw;
#pragma unroll
    for (int o = 0; o < HID; o++)
        fb[o * HW_] = fmaxf(acc[o] * inv_s[o] + beta_s[o], 0.f);
}

// ============================================================
// K2 (tiled): off = relu(bn3(1x1( relu(bn2(3x3(f))) )))
// ============================================================
__global__ __launch_bounds__(256)
void k2_offsets(const float* __restrict__ wdw,
                const float* __restrict__ g2, const float* __restrict__ b2,
                const float* __restrict__ m2, const float* __restrict__ v2,
                const float* __restrict__ wc2,
                const float* __restrict__ g3, const float* __restrict__ b3,
                const float* __restrict__ m3, const float* __restrict__ v3) {
    __shared__ float fs[HID * 18 * 18];
    __shared__ float wdw_s[OFC * HID * 9];
    __shared__ float wc2_s[OFC * OFC];
    __shared__ float inv2_s[OFC], beta2_s[OFC], inv3_s[OFC], beta3_s[OFC];
    int tid = threadIdx.x;

    int blk = blockIdx.x;
    int b = blk >> 6, t = blk & 63;
    int h0 = (t >> 3) << 4, w0 = (t & 7) << 4;

    for (int e = tid; e < OFC * HID * 9; e += 256) wdw_s[e] = wdw[e];
    for (int e = tid; e < OFC * OFC; e += 256)     wc2_s[e] = wc2[e];
    if (tid < OFC) {
        float i2 = g2[tid] * rsqrtf(v2[tid] + 1e-5f);
        inv2_s[tid] = i2; beta2_s[tid] = b2[tid] - m2[tid] * i2;
        float i3 = g3[tid] * rsqrtf(v3[tid] + 1e-5f);
        inv3_s[tid] = i3; beta3_s[tid] = b3[tid] - m3[tid] * i3;
    }

    const float* fb = g_f + (size_t)b * HID * HW_;
    for (int e = tid; e < HID * 324; e += 256) {
        int ci = e / 324, r = e - ci * 324;
        int hh = r / 18, ww = r - hh * 18;
        int h = h0 - 1 + hh, w = w0 - 1 + ww;
        float v = 0.f;
        if (h >= 0 && h < H_ && w >= 0 && w < W_)
            v = fb[ci * HW_ + h * W_ + w];
        fs[e] = v;
    }
    __syncthreads();

    int ty2 = tid >> 4, tx2 = tid & 15;
    float acc[OFC];
#pragma unroll
    for (int o = 0; o < OFC; o++) acc[o] = 0.f;

    for (int ci = 0; ci < HID; ci++) {
        float fv[9];
        const float* fsc = fs + ci * 324;
#pragma unroll
        for (int dh = 0; dh < 3; dh++)
#pragma unroll
            for (int dw = 0; dw < 3; dw++)
                fv[dh * 3 + dw] = fsc[(ty2 + dh) * 18 + (tx2 + dw)];
        const float* wp = wdw_s + ci * 9;
#pragma unroll
        for (int o = 0; o < OFC; o++) {
            const float* wo = wp + o * (HID * 9);
            float a = acc[o];
#pragma unroll
            for (int k = 0; k < 9; k++) a += wo[k] * fv[k];
            acc[o] = a;
        }
    }
    float tv[OFC];
#pragma unroll
    for (int o = 0; o < OFC; o++)
        tv[o] = fmaxf(acc[o] * inv2_s[o] + beta2_s[o], 0.f);

    int h = h0 + ty2, w = w0 + tx2;
    float* op = g_off + (size_t)b * OFC * HW_ + h * W_ + w;
#pragma unroll
    for (int o2 = 0; o2 < OFC; o2++) {
        float a = 0.f;
#pragma unroll
        for (int o = 0; o < OFC; o++) a += wc2_s[o2 * OFC + o] * tv[o];
        op[o2 * HW_] = fmaxf(a * inv3_s[o2] + beta3_s[o2], 0.f);
    }
}

// ============================================================
// K3: fused bilinear sampler + SGEMM (f32x2) + residual
//   gather: warp = 4 samples x 8 channels (lane = sl*8+cil)
//           each corner LDG.32 touches only ~4 sectors per warp
//   slab pitch 132 floats (16B-aligned rows, conflict-light STS)
// ============================================================
#define APITCH 132
#define A2N (72*APITCH)
#define K3_SMEM (576*32 + 2*A2N*4)   // 18432 + 76032 = 94464

__global__ __launch_bounds__(256, 2)
void k3_main(const float* __restrict__ x, float* __restrict__ out) {
    extern __shared__ char smem[];
    int4*   idx_s = (int4*)smem;                   // [576] (n*64+m), premult by 64
    float4* wgt_s = (float4*)(smem + 9216);        // [576]
    float*  a2    = (float*)(smem + 18432);        // [2][72][APITCH]

    int tid = threadIdx.x;
    int blk = blockIdx.x;
    int b = blk >> 8;
    int tile = blk & 255;
    int h0 = (tile >> 4) << 3;
    int w0 = (tile & 15) << 3;

    // ---- bilinear metadata: 64 px x 9 pts ----
    const float* offp = g_off + (size_t)b * OFC * HW_;
    for (int e = tid; e < 64 * NPT; e += 256) {
        int m = e / NPT, n = e - m * NPT;
        int h = h0 + (m >> 3), w = w0 + (m & 7);
        int hw = h * W_ + w;
        float offx = offp[n * HW_ + hw];
        float offy = offp[(NPT + n) * HW_ + hw];
        float px = (float)(h + 1) + (float)(n / 3 - 1) + offx;
        float py = (float)(w + 1) + (float)(n % 3 - 1) + offy;
        float flx = floorf(px), fly = floorf(py);
        float qltx = fminf(fmaxf(flx, 0.f), 129.f);
        float qlty = fminf(fmaxf(fly, 0.f), 129.f);
        float qrbx = fminf(fmaxf(flx + 1.f, 0.f), 129.f);
        float qrby = fminf(fmaxf(fly + 1.f, 0.f), 129.f);
        px = fminf(fmaxf(px, 0.f), 129.f);
        py = fminf(fmaxf(py, 0.f), 129.f);
        float gxl = 1.f + qltx - px, gxr = 1.f - qrbx + px;
        float gyl = 1.f + qlty - py, gyr = 1.f - qrby + py;
        float4 g;
        g.x = gxl * gyl; g.y = gxr * gyr; g.z = gxl * gyr; g.w = gxr * gyl;
        int ltx = (int)qltx, lty = (int)qlty, rbx = (int)qrbx, rby = (int)qrby;
        int4 id;
        id.x = (ltx * WP_ + lty) << 6;    // premultiplied by C_=64
        id.y = (rbx * WP_ + rby) << 6;
        id.z = (ltx * WP_ + rby) << 6;
        id.w = (rbx * WP_ + lty) << 6;
        idx_s[n * 64 + m] = id;
        wgt_s[n * 64 + m] = g;
    }
    __syncthreads();

    const float* xpb = g_xp + (size_t)b * HWP_ * C_;
    const int cil   = tid & 7;           // channel within chunk
    const int sbase = tid >> 3;          // sample group 0..31

    // warp-cooperative gather of one 8-channel chunk
#define GATHER_CHUNK(ab, cc)                                                  \
    {                                                                         \
        const float* xpc = xpb + (cc) * 8 + cil;                              \
        _Pragma("unroll 3")                                                   \
        for (int it = 0; it < 18; it++) {                                     \
            int s = it * 32 + sbase;      /* 0..575 = n*64+m */               \
            int4 id = idx_s[s];                                               \
            float4 g = wgt_s[s];                                              \
            float v = g.x * xpc[id.x] + g.y * xpc[id.y]                       \
                    + g.z * xpc[id.z] + g.w * xpc[id.w];                      \
            int n = s >> 6, m = s & 63;                                       \
            *(float2*)((ab) + (n * 8 + cil) * APITCH + (m << 1)) =            \
                make_float2(v, v);                                            \
        }                                                                     \
    }

    GATHER_CHUNK(a2, 0)

    int tx = tid & 15, ty = tid >> 4;
    unsigned long long acc[4][2];
#pragma unroll
    for (int i = 0; i < 4; i++) { acc[i][0] = 0ull; acc[i][1] = 0ull; }

    const int tyo = ty << 3;
    const int txo = tx << 2;

    // ---- pipelined chunk loop: gather(c+1) overlaps GEMM(c) ----
    for (int c = 0; c < 8; c++) {
        __syncthreads();

        if (c < 7) {
            float* ab = a2 + ((c + 1) & 1) * A2N;
            GATHER_CHUNK(ab, c + 1)
        }

        const float* ab = a2 + (c & 1) * A2N;
        const float* wp = g_wt + c * 72 * C_ + txo;   // permuted B rows (L2/L1-hot)
#pragma unroll 8
        for (int k = 0; k < 72; k++) {
            ulonglong2 bb = *reinterpret_cast<const ulonglong2*>(wp + (k << 6));
            ulonglong2 aA = *reinterpret_cast<const ulonglong2*>(ab + k * APITCH + tyo);
            ulonglong2 aB = *reinterpret_cast<const ulonglong2*>(ab + k * APITCH + tyo + 4);
            FMA2(acc[0][0], aA.x, bb.x); FMA2(acc[0][1], aA.x, bb.y);
            FMA2(acc[1][0], aA.y, bb.x); FMA2(acc[1][1], aA.y, bb.y);
            FMA2(acc[2][0], aB.x, bb.x); FMA2(acc[2][1], aB.x, bb.y);
            FMA2(acc[3][0], aB.y, bb.x); FMA2(acc[3][1], aB.y, bb.y);
        }
    }

    // ---- epilogue: stage through smem (buf0 dead) for coalesced stores ----
    float* sa = a2;  // [oc][m]
#pragma unroll
    for (int pi = 0; pi < 4; pi++) {
        int m = (ty << 2) + pi;
#pragma unroll
        for (int j = 0; j < 2; j++) {
            unsigned long long v = acc[pi][j];
            float lo = __uint_as_float((unsigned)(v & 0xffffffffull));
            float hi = __uint_as_float((unsigned)(v >> 32));
            sa[(txo + 2 * j) * 64 + m]     = lo;
            sa[(txo + 2 * j + 1) * 64 + m] = hi;
        }
    }
    __syncthreads();

    for (int e = tid; e < 64 * 64; e += 256) {
        int oc = e >> 6, m = e & 63;
        int h = h0 + (m >> 3), w = w0 + (m & 7);
        int gi = ((b * C_ + oc) * H_ + h) * W_ + w;
        out[gi] = x[gi] + sa[e];
    }
}

// ============================================================
extern "C" void kernel_launch(void* const* d_in, const int* in_sizes, int n_in,
                              void* d_out, int out_size) {
    const float* x       = (const float*)d_in[0];
    const float* w_conv1 = (const float*)d_in[1];
    const float* g1 = (const float*)d_in[2];
    const float* b1 = (const float*)d_in[3];
    const float* m1 = (const float*)d_in[4];
    const float* v1 = (const float*)d_in[5];
    const float* w_dw = (const float*)d_in[6];
    const float* g2 = (const float*)d_in[7];
    const float* b2 = (const float*)d_in[8];
    const float* m2 = (const float*)d_in[9];
    const float* v2 = (const float*)d_in[10];
    const float* w_conv2 = (const float*)d_in[11];
    const float* g3 = (const float*)d_in[12];
    const float* b3 = (const float*)d_in[13];
    const float* m3 = (const float*)d_in[14];
    const float* v3 = (const float*)d_in[15];
    const float* w_out = (const float*)d_in[16];
    float* out = (float*)d_out;

    cudaFuncSetAttribute(k3_main, cudaFuncAttributeMaxDynamicSharedMemorySize, K3_SMEM);

    k_padT<<<PAD_BLKS + W0_BLKS, 256>>>(x, w_out);
    k1_conv1<<<PIXT / 256, 256>>>(x, w_conv1, g1, b1, m1, v1);
    k2_offsets<<<128, 256>>>(w_dw, g2, b2, m2, v2, w_conv2, g3, b3, m3, v3);
    k3_main<<<B_ * (H_ / 8) * (W_ / 8), 256, K3_SMEM>>>(x, out);
}